// round 8
// baseline (speedup 1.0000x reference)
#include <cuda_runtime.h>
#include <cstdint>
#include <cstddef>

#define Hh   16
#define Dd   1024
#define DHd  64
#define Bb   4
#define Nn   2048
#define MTOT (Bb*Nn)   // 8192

// ---------------- scratch (static device globals; no allocation) ----------------
__device__ float g_q[(size_t)Bb*Hh*Nn*DHd];     // (b,h,n,dh)
__device__ float g_k[(size_t)Bb*Hh*Nn*DHd];
__device__ float g_v[(size_t)Bb*Hh*Nn*DHd];
__device__ float g_ctx[(size_t)MTOT*Dd];        // (b,n, h*dh)

__device__ __forceinline__ uint32_t f2tf32(float x) {
    uint32_t r;
    asm("cvt.rna.tf32.f32 %0, %1;" : "=r"(r) : "f"(x));
    return r;
}

// ====== tf32 mma.sync NT GEMM: C = A(M,K) * W(N,K)^T ; 128x128 tile, K=1024 =====
// 8 warps in 4(M) x 2(N); warp tile 32x64 = 2 x 8 m16n8k8 fragments.
// MODE 0: C row-major (M x 1024). MODE 1: scatter into (b,h,n,dh).
template<int MODE>
__global__ __launch_bounds__(256)
void gemm_mma(const float* __restrict__ A, const float* __restrict__ W,
              float* __restrict__ C)
{
    __shared__ float As[128*36];   // [row][k], stride 36 (bank = 4*row + k)
    __shared__ float Bs[128*36];

    const int tid  = threadIdx.x;
    const int wid  = tid >> 5;
    const int lane = tid & 31;
    const int bx = blockIdx.x;     // N tile (0..7)
    const int by = blockIdx.y;     // M tile (0..63)

    const int wm = (wid >> 1) * 32;   // warp M offset in tile
    const int wn = (wid & 1)  * 64;   // warp N offset in tile
    const int gq = lane >> 2;         // 0..7
    const int j4 = lane & 3;          // 0..3

    // copy indexing: 2 threads per row, 16 floats each
    const int cr = tid >> 1;              // 0..127
    const int cc = (tid & 1) * 16;        // 0 or 16
    const float* Ap = A + (size_t)(by*128 + cr)*1024 + cc;
    const float* Wp = W + (size_t)(bx*128 + cr)*1024 + cc;

    float acc[2][8][4];
    #pragma unroll
    for (int mi = 0; mi < 2; ++mi)
        #pragma unroll
        for (int ni = 0; ni < 8; ++ni)
            #pragma unroll
            for (int q = 0; q < 4; ++q) acc[mi][ni][q] = 0.f;

    float4 pa[4], pb[4];
    #pragma unroll
    for (int i = 0; i < 4; ++i) {
        pa[i] = *(const float4*)(Ap + 4*i);
        pb[i] = *(const float4*)(Wp + 4*i);
    }

    for (int c = 0; c < 32; ++c) {
        __syncthreads();   // previous chunk's fragment reads done
        #pragma unroll
        for (int i = 0; i < 4; ++i) {
            uint32_t* da = (uint32_t*)&As[cr*36 + cc + 4*i];
            da[0] = f2tf32(pa[i].x); da[1] = f2tf32(pa[i].y);
            da[2] = f2tf32(pa[i].z); da[3] = f2tf32(pa[i].w);
            uint32_t* db = (uint32_t*)&Bs[cr*36 + cc + 4*i];
            db[0] = f2tf32(pb[i].x); db[1] = f2tf32(pb[i].y);
            db[2] = f2tf32(pb[i].z); db[3] = f2tf32(pb[i].w);
        }
        __syncthreads();

        if (c < 31) {   // prefetch next chunk, overlapping the MMAs below
            #pragma unroll
            for (int i = 0; i < 4; ++i) {
                pa[i] = *(const float4*)(Ap + (c+1)*32 + 4*i);
                pb[i] = *(const float4*)(Wp + (c+1)*32 + 4*i);
            }
        }

        #pragma unroll
        for (int ks = 0; ks < 4; ++ks) {
            const int k0 = ks * 8;
            uint32_t af[2][4];
            #pragma unroll
            for (int mi = 0; mi < 2; ++mi) {
                const int r = wm + mi*16 + gq;
                af[mi][0] = __float_as_uint(As[ r    *36 + k0 + j4    ]);
                af[mi][1] = __float_as_uint(As[(r+8)*36 + k0 + j4    ]);
                af[mi][2] = __float_as_uint(As[ r    *36 + k0 + j4 + 4]);
                af[mi][3] = __float_as_uint(As[(r+8)*36 + k0 + j4 + 4]);
            }
            uint32_t bf[8][2];
            #pragma unroll
            for (int ni = 0; ni < 8; ++ni) {
                const int n = wn + ni*8 + gq;
                bf[ni][0] = __float_as_uint(Bs[n*36 + k0 + j4    ]);
                bf[ni][1] = __float_as_uint(Bs[n*36 + k0 + j4 + 4]);
            }
            #pragma unroll
            for (int mi = 0; mi < 2; ++mi)
                #pragma unroll
                for (int ni = 0; ni < 8; ++ni)
                    asm volatile(
                        "mma.sync.aligned.m16n8k8.row.col.f32.tf32.tf32.f32 "
                        "{%0,%1,%2,%3}, {%4,%5,%6,%7}, {%8,%9}, {%0,%1,%2,%3};"
                        : "+f"(acc[mi][ni][0]), "+f"(acc[mi][ni][1]),
                          "+f"(acc[mi][ni][2]), "+f"(acc[mi][ni][3])
                        : "r"(af[mi][0]), "r"(af[mi][1]),
                          "r"(af[mi][2]), "r"(af[mi][3]),
                          "r"(bf[ni][0]), "r"(bf[ni][1]));
        }
    }

    // epilogue: D fragment c0,c1 at (row, 2*j4+{0,1}); c2,c3 at (row+8, ...)
    #pragma unroll
    for (int mi = 0; mi < 2; ++mi) {
        #pragma unroll
        for (int ni = 0; ni < 8; ++ni) {
            const int row = by*128 + wm + mi*16 + gq;
            const int col = bx*128 + wn + ni*8 + 2*j4;
            if (MODE == 0) {
                *(float2*)(C + (size_t)row*1024 + col) =
                    make_float2(acc[mi][ni][0], acc[mi][ni][1]);
                *(float2*)(C + (size_t)(row+8)*1024 + col) =
                    make_float2(acc[mi][ni][2], acc[mi][ni][3]);
            } else {
                const int hh = col >> 6;        // float2 stays inside one head
                const int d0 = col & 63;
                const int bb = row >> 11;       // rows row/row+8 share bb (tile-aligned)
                const int nq = row & 2047;
                float* o0 = g_ctx; // dummy init avoided; compute directly:
                o0 = C + ((((size_t)bb*Hh + hh)*Nn + nq)*DHd + d0);
                *(float2*)o0 = make_float2(acc[mi][ni][0], acc[mi][ni][1]);
                float* o1 = C + ((((size_t)bb*Hh + hh)*Nn + (nq+8))*DHd + d0);
                *(float2*)o1 = make_float2(acc[mi][ni][2], acc[mi][ni][3]);
            }
        }
    }
}

// ---------------- fused flash attention: per (b,h), BM=128 queries x BN=64 keys --
// Q/K/V in (b,h,n,dh); output ctx in (b,n,h*dh).
__global__ __launch_bounds__(256, 2)
void attn_kernel(const float* __restrict__ Q, const float* __restrict__ Kg,
                 const float* __restrict__ Vg, float* __restrict__ O)
{
    extern __shared__ float smf[];
    float* Qt = smf;              // [64][132]  Qt[d*132 + r]   (transposed, pre-scaled)
    float* KP = smf + 64*132;     // K phase: [d*68 + c] ; P phase: [(jcol)*132 + r]
    float* Vs = KP + 64*132;      // [j*64 + d]

    const int bh = blockIdx.y;           // b*H + h
    const int q0 = blockIdx.x * 128;
    const float* Qb = Q  + ((size_t)bh*Nn + q0)*DHd;
    const float* Kb = Kg + (size_t)bh*Nn*DHd;
    const float* Vb = Vg + (size_t)bh*Nn*DHd;

    const int tid = threadIdx.x;
    const int tx = tid & 15;             // col group: cols 4*tx..+3
    const int ty = tid >> 4;             // row group: rows 8*ty..+7

    // --- load Q tile (128x64), transpose + fold in softmax scale 1/sqrt(64)
    #pragma unroll
    for (int it = 0; it < 8; ++it) {
        int lin = tid + 256*it;          // 0..2047
        int r = lin >> 4;                // 0..127
        int f = (lin & 15) * 4;          // 0..60
        float4 v = *(const float4*)(Qb + r*64 + f);
        Qt[(f+0)*132 + r] = v.x * 0.125f;
        Qt[(f+1)*132 + r] = v.y * 0.125f;
        Qt[(f+2)*132 + r] = v.z * 0.125f;
        Qt[(f+3)*132 + r] = v.w * 0.125f;
    }

    float ctx[8][4];
    float m_i[8], l_i[8];
    #pragma unroll
    for (int i = 0; i < 8; ++i) {
        m_i[i] = -1e30f; l_i[i] = 0.f;
        #pragma unroll
        for (int j = 0; j < 4; ++j) ctx[i][j] = 0.f;
    }

    for (int kt = 0; kt < Nn/64; ++kt) {
        __syncthreads();   // previous PV reads of KP/Vs complete

        const float* Kt0 = Kb + (size_t)kt*64*DHd;
        const float* Vt0 = Vb + (size_t)kt*64*DHd;
        #pragma unroll
        for (int it = 0; it < 4; ++it) {
            int lin = tid + 256*it;      // 0..1023
            int c = lin >> 4;            // 0..63 key row
            int f = (lin & 15) * 4;
            float4 kv = *(const float4*)(Kt0 + c*64 + f);
            KP[(f+0)*68 + c] = kv.x;
            KP[(f+1)*68 + c] = kv.y;
            KP[(f+2)*68 + c] = kv.z;
            KP[(f+3)*68 + c] = kv.w;
            *(float4*)(Vs + c*64 + f) = *(const float4*)(Vt0 + c*64 + f);
        }
        __syncthreads();

        // --- S = (Q*scale) @ K^T   : s[i][j], rows 8ty+i, cols 4tx+j
        float s[8][4];
        #pragma unroll
        for (int i = 0; i < 8; ++i)
            #pragma unroll
            for (int j = 0; j < 4; ++j) s[i][j] = 0.f;

        #pragma unroll 8
        for (int d = 0; d < 64; ++d) {
            float4 qa = *(const float4*)(Qt + d*132 + 8*ty);
            float4 qb = *(const float4*)(Qt + d*132 + 8*ty + 4);
            float qr[8] = {qa.x,qa.y,qa.z,qa.w,qb.x,qb.y,qb.z,qb.w};
            float4 k4 = *(const float4*)(KP + d*68 + 4*tx);
            float kr[4] = {k4.x, k4.y, k4.z, k4.w};
            #pragma unroll
            for (int i = 0; i < 8; ++i)
                #pragma unroll
                for (int j = 0; j < 4; ++j)
                    s[i][j] += qr[i]*kr[j];
        }

        // --- online softmax stats (16 lanes share each row)
        float alpha[8];
        #pragma unroll
        for (int i = 0; i < 8; ++i) {
            float mx = fmaxf(fmaxf(s[i][0], s[i][1]), fmaxf(s[i][2], s[i][3]));
            #pragma unroll
            for (int o = 1; o < 16; o <<= 1)
                mx = fmaxf(mx, __shfl_xor_sync(0xffffffffu, mx, o));
            float mn = fmaxf(m_i[i], mx);
            alpha[i] = __expf(m_i[i] - mn);
            m_i[i] = mn;
            float rs = 0.f;
            #pragma unroll
            for (int j = 0; j < 4; ++j) {
                s[i][j] = __expf(s[i][j] - mn);
                rs += s[i][j];
            }
            #pragma unroll
            for (int o = 1; o < 16; o <<= 1)
                rs += __shfl_xor_sync(0xffffffffu, rs, o);
            l_i[i] = l_i[i]*alpha[i] + rs;
        }

        __syncthreads();   // all S reads of KP(K) done
        // --- write P transposed into KP: P[jcol][row], stride 132
        #pragma unroll
        for (int j = 0; j < 4; ++j) {
            float* dst = KP + (4*tx + j)*132 + 8*ty;
            *(float4*)dst     = make_float4(s[0][j], s[1][j], s[2][j], s[3][j]);
            *(float4*)(dst+4) = make_float4(s[4][j], s[5][j], s[6][j], s[7][j]);
        }
        __syncthreads();

        // --- ctx = ctx*alpha + P @ V
        #pragma unroll
        for (int i = 0; i < 8; ++i) {
            ctx[i][0] *= alpha[i]; ctx[i][1] *= alpha[i];
            ctx[i][2] *= alpha[i]; ctx[i][3] *= alpha[i];
        }
        #pragma unroll 4
        for (int jj = 0; jj < 64; ++jj) {
            float4 pa = *(const float4*)(KP + jj*132 + 8*ty);
            float4 pb = *(const float4*)(KP + jj*132 + 8*ty + 4);
            float pr[8] = {pa.x,pa.y,pa.z,pa.w,pb.x,pb.y,pb.z,pb.w};
            float4 v = *(const float4*)(Vs + jj*64 + 4*tx);
            #pragma unroll
            for (int i = 0; i < 8; ++i) {
                ctx[i][0] += pr[i]*v.x;
                ctx[i][1] += pr[i]*v.y;
                ctx[i][2] += pr[i]*v.z;
                ctx[i][3] += pr[i]*v.w;
            }
        }
    }

    // --- epilogue: normalize, write ctx in (b, n, h*64+d)
    const int bb = bh >> 4;
    const int hh = bh & 15;
    #pragma unroll
    for (int i = 0; i < 8; ++i) {
        float inv = 1.0f / l_i[i];
        int n = q0 + 8*ty + i;
        float4 o = make_float4(ctx[i][0]*inv, ctx[i][1]*inv,
                               ctx[i][2]*inv, ctx[i][3]*inv);
        *(float4*)(O + (((size_t)bb*Nn + n)*Hh + hh)*DHd + 4*tx) = o;
    }
}

// ---------------- launch ---------------------------------------------------------
extern "C" void kernel_launch(void* const* d_in, const int* in_sizes, int n_in,
                              void* d_out, int out_size)
{
    const float* queries = (const float*)d_in[0];
    const float* keys    = (const float*)d_in[1];
    const float* values  = (const float*)d_in[2];
    const float* Wq      = (const float*)d_in[3];
    const float* Wk      = (const float*)d_in[4];
    const float* Wv      = (const float*)d_in[5];
    const float* Wo      = (const float*)d_in[6];
    float* out = (float*)d_out;

    float *qp, *kp, *vp, *cp;
    cudaGetSymbolAddress((void**)&qp, g_q);
    cudaGetSymbolAddress((void**)&kp, g_k);
    cudaGetSymbolAddress((void**)&vp, g_v);
    cudaGetSymbolAddress((void**)&cp, g_ctx);

    dim3 ggrid(1024/128, MTOT/128);   // (8, 64)
    gemm_mma<1><<<ggrid, 256>>>(queries, Wq, qp);
    gemm_mma<1><<<ggrid, 256>>>(keys,    Wk, kp);
    gemm_mma<1><<<ggrid, 256>>>(values,  Wv, vp);

    const int asmem = (64*132 + 64*132 + 64*64) * (int)sizeof(float);  // 83968 B
    cudaFuncSetAttribute(attn_kernel,
                         cudaFuncAttributeMaxDynamicSharedMemorySize, asmem);
    dim3 agrid(Nn/128, Bb*Hh);        // (16, 64)
    attn_kernel<<<agrid, 256, asmem>>>(qp, kp, vp, cp);

    gemm_mma<0><<<ggrid, 256>>>(cp, Wo, out);
}

// round 9
// speedup vs baseline: 1.7367x; 1.7367x over previous
#include <cuda_runtime.h>
#include <cuda_bf16.h>
#include <cstdint>
#include <cstddef>

#define Hh   16
#define Dd   1024
#define DHd  64
#define Bb   4
#define Nn   2048
#define MTOT (Bb*Nn)   // 8192

// ---------------- scratch (static device globals; no allocation) ----------------
__device__ float g_q[(size_t)Bb*Hh*Nn*DHd];     // (b,h,n,dh)
__device__ float g_k[(size_t)Bb*Hh*Nn*DHd];
__device__ float g_v[(size_t)Bb*Hh*Nn*DHd];
__device__ float g_ctx[(size_t)MTOT*Dd];        // (b,n, h*dh)

__device__ __forceinline__ uint32_t f2tf32(float x) {
    uint32_t r;
    asm("cvt.rna.tf32.f32 %0, %1;" : "=r"(r) : "f"(x));
    return r;
}

// pack two floats -> bf16x2 (lo -> bits[15:0], hi -> bits[31:16])
__device__ __forceinline__ uint32_t pk(float lo, float hi) {
    __nv_bfloat162 h = __float22bfloat162_rn(make_float2(lo, hi));
    return *(uint32_t*)&h;
}
// residuals vs the bf16 in a packed pair (exact: bf16->f32 is a shift)
__device__ __forceinline__ float rlo(float f, uint32_t p) { return f - __uint_as_float(p << 16); }
__device__ __forceinline__ float rhi(float f, uint32_t p) { return f - __uint_as_float(p & 0xffff0000u); }

#define MMA_BF16(d, a, b0, b1) \
    asm volatile("mma.sync.aligned.m16n8k16.row.col.f32.bf16.bf16.f32 " \
        "{%0,%1,%2,%3},{%4,%5,%6,%7},{%8,%9},{%0,%1,%2,%3};" \
        : "+f"((d)[0]), "+f"((d)[1]), "+f"((d)[2]), "+f"((d)[3]) \
        : "r"((a)[0]), "r"((a)[1]), "r"((a)[2]), "r"((a)[3]), "r"(b0), "r"(b1))

// ====== tf32 mma.sync NT GEMM: C = A(M,K) * W(N,K)^T ; 128x128 tile, K=1024 =====
// 8 warps in 4(M) x 2(N); warp tile 32x64 = 2 x 8 m16n8k8 fragments.
// MODE 0: C row-major (M x 1024). MODE 1: scatter into (b,h,n,dh).
template<int MODE>
__global__ __launch_bounds__(256)
void gemm_mma(const float* __restrict__ A, const float* __restrict__ W,
              float* __restrict__ C)
{
    __shared__ float As[128*36];   // [row][k], stride 36 (bank = 4*row + k)
    __shared__ float Bs[128*36];

    const int tid  = threadIdx.x;
    const int wid  = tid >> 5;
    const int lane = tid & 31;
    const int bx = blockIdx.x;     // N tile (0..7)
    const int by = blockIdx.y;     // M tile (0..63)

    const int wm = (wid >> 1) * 32;   // warp M offset in tile
    const int wn = (wid & 1)  * 64;   // warp N offset in tile
    const int gq = lane >> 2;         // 0..7
    const int j4 = lane & 3;          // 0..3

    const int cr = tid >> 1;              // 0..127
    const int cc = (tid & 1) * 16;        // 0 or 16
    const float* Ap = A + (size_t)(by*128 + cr)*1024 + cc;
    const float* Wp = W + (size_t)(bx*128 + cr)*1024 + cc;

    float acc[2][8][4];
    #pragma unroll
    for (int mi = 0; mi < 2; ++mi)
        #pragma unroll
        for (int ni = 0; ni < 8; ++ni)
            #pragma unroll
            for (int q = 0; q < 4; ++q) acc[mi][ni][q] = 0.f;

    float4 pa[4], pb[4];
    #pragma unroll
    for (int i = 0; i < 4; ++i) {
        pa[i] = *(const float4*)(Ap + 4*i);
        pb[i] = *(const float4*)(Wp + 4*i);
    }

    for (int c = 0; c < 32; ++c) {
        __syncthreads();
        #pragma unroll
        for (int i = 0; i < 4; ++i) {
            uint32_t* da = (uint32_t*)&As[cr*36 + cc + 4*i];
            da[0] = f2tf32(pa[i].x); da[1] = f2tf32(pa[i].y);
            da[2] = f2tf32(pa[i].z); da[3] = f2tf32(pa[i].w);
            uint32_t* db = (uint32_t*)&Bs[cr*36 + cc + 4*i];
            db[0] = f2tf32(pb[i].x); db[1] = f2tf32(pb[i].y);
            db[2] = f2tf32(pb[i].z); db[3] = f2tf32(pb[i].w);
        }
        __syncthreads();

        if (c < 31) {
            #pragma unroll
            for (int i = 0; i < 4; ++i) {
                pa[i] = *(const float4*)(Ap + (c+1)*32 + 4*i);
                pb[i] = *(const float4*)(Wp + (c+1)*32 + 4*i);
            }
        }

        #pragma unroll
        for (int ks = 0; ks < 4; ++ks) {
            const int k0 = ks * 8;
            uint32_t af[2][4];
            #pragma unroll
            for (int mi = 0; mi < 2; ++mi) {
                const int r = wm + mi*16 + gq;
                af[mi][0] = __float_as_uint(As[ r    *36 + k0 + j4    ]);
                af[mi][1] = __float_as_uint(As[(r+8)*36 + k0 + j4    ]);
                af[mi][2] = __float_as_uint(As[ r    *36 + k0 + j4 + 4]);
                af[mi][3] = __float_as_uint(As[(r+8)*36 + k0 + j4 + 4]);
            }
            uint32_t bf[8][2];
            #pragma unroll
            for (int ni = 0; ni < 8; ++ni) {
                const int n = wn + ni*8 + gq;
                bf[ni][0] = __float_as_uint(Bs[n*36 + k0 + j4    ]);
                bf[ni][1] = __float_as_uint(Bs[n*36 + k0 + j4 + 4]);
            }
            #pragma unroll
            for (int mi = 0; mi < 2; ++mi)
                #pragma unroll
                for (int ni = 0; ni < 8; ++ni)
                    asm volatile(
                        "mma.sync.aligned.m16n8k8.row.col.f32.tf32.tf32.f32 "
                        "{%0,%1,%2,%3}, {%4,%5,%6,%7}, {%8,%9}, {%0,%1,%2,%3};"
                        : "+f"(acc[mi][ni][0]), "+f"(acc[mi][ni][1]),
                          "+f"(acc[mi][ni][2]), "+f"(acc[mi][ni][3])
                        : "r"(af[mi][0]), "r"(af[mi][1]),
                          "r"(af[mi][2]), "r"(af[mi][3]),
                          "r"(bf[ni][0]), "r"(bf[ni][1]));
        }
    }

    #pragma unroll
    for (int mi = 0; mi < 2; ++mi) {
        #pragma unroll
        for (int ni = 0; ni < 8; ++ni) {
            const int row = by*128 + wm + mi*16 + gq;
            const int col = bx*128 + wn + ni*8 + 2*j4;
            if (MODE == 0) {
                *(float2*)(C + (size_t)row*1024 + col) =
                    make_float2(acc[mi][ni][0], acc[mi][ni][1]);
                *(float2*)(C + (size_t)(row+8)*1024 + col) =
                    make_float2(acc[mi][ni][2], acc[mi][ni][3]);
            } else {
                const int hh = col >> 6;        // float2 stays inside one head
                const int d0 = col & 63;
                const int bb = row >> 11;
                const int nq = row & 2047;
                float* o0 = C + ((((size_t)bb*Hh + hh)*Nn + nq)*DHd + d0);
                *(float2*)o0 = make_float2(acc[mi][ni][0], acc[mi][ni][1]);
                float* o1 = C + ((((size_t)bb*Hh + hh)*Nn + (nq+8))*DHd + d0);
                *(float2*)o1 = make_float2(acc[mi][ni][2], acc[mi][ni][3]);
            }
        }
    }
}

// ========= tensor-core flash attention (bf16x2 3-term), BM=128, BN=64 ===========
// Q/K/V in (b,h,n,dh) fp32. Output ctx in (b,n,h*dh) fp32.
// smem per buffer (bf16 elems): Khi[64][72] Klo[64][72] Vthi[64][72] Vtlo[64][72]
static const int ABUF = 4 * 64 * 72;            // 18432 bf16 elems per buffer

__device__ __forceinline__ void ldg_kv(const float* __restrict__ Kt0,
                                       const float* __restrict__ Vt0,
                                       int tid, float* kr, float* vr)
{
    const float* kp = Kt0 + (tid >> 2) * 64 + (tid & 3) * 16;
    #pragma unroll
    for (int i = 0; i < 4; ++i) {
        float4 t = *(const float4*)(kp + 4*i);
        kr[4*i] = t.x; kr[4*i+1] = t.y; kr[4*i+2] = t.z; kr[4*i+3] = t.w;
    }
    const float* vp = Vt0 + ((tid >> 6) * 16) * 64 + (tid & 63);
    #pragma unroll
    for (int t = 0; t < 16; ++t) vr[t] = vp[t * 64];
}

__device__ __forceinline__ void sts_kv(__nv_bfloat16* buf, int tid,
                                       const float* kr, const float* vr)
{
    // K rows: key = tid>>2, dh cols (tid&3)*16 .. +15 ; stride 72
    __nv_bfloat16* kh = buf + (tid >> 2) * 72 + (tid & 3) * 16;
    __nv_bfloat16* kl = kh + 4608;
    #pragma unroll
    for (int g = 0; g < 4; ++g) {
        uint32_t h0 = pk(kr[4*g],   kr[4*g+1]);
        uint32_t h1 = pk(kr[4*g+2], kr[4*g+3]);
        *(uint2*)(kh + 4*g) = make_uint2(h0, h1);
        uint32_t l0 = pk(rlo(kr[4*g],   h0), rhi(kr[4*g+1], h0));
        uint32_t l1 = pk(rlo(kr[4*g+2], h1), rhi(kr[4*g+3], h1));
        *(uint2*)(kl + 4*g) = make_uint2(l0, l1);
    }
    // Vt rows: dh = tid&63, key cols (tid>>6)*16 .. +15 ; stride 72
    __nv_bfloat16* vh = buf + 9216 + (tid & 63) * 72 + (tid >> 6) * 16;
    __nv_bfloat16* vl = vh + 4608;
    #pragma unroll
    for (int g = 0; g < 4; ++g) {
        uint32_t h0 = pk(vr[4*g],   vr[4*g+1]);
        uint32_t h1 = pk(vr[4*g+2], vr[4*g+3]);
        *(uint2*)(vh + 4*g) = make_uint2(h0, h1);
        uint32_t l0 = pk(rlo(vr[4*g],   h0), rhi(vr[4*g+1], h0));
        uint32_t l1 = pk(rlo(vr[4*g+2], h1), rhi(vr[4*g+3], h1));
        *(uint2*)(vl + 4*g) = make_uint2(l0, l1);
    }
}

__global__ __launch_bounds__(256, 1)
void attn_mma(const float* __restrict__ Q, const float* __restrict__ Kg,
              const float* __restrict__ Vg, float* __restrict__ O)
{
    extern __shared__ __align__(16) __nv_bfloat16 smb[];

    const int bh = blockIdx.y;            // b*H + h
    const int q0 = blockIdx.x * 128;
    const int tid  = threadIdx.x;
    const int w    = tid >> 5;            // warp 0..7 -> q rows 16w..16w+15
    const int lane = tid & 31;
    const int gq = lane >> 2;
    const int j4 = lane & 3;

    const float* Kb = Kg + (size_t)bh * Nn * DHd;
    const float* Vb = Vg + (size_t)bh * Nn * DHd;

    // ---- Q fragments in registers (pre-scaled by 1/sqrt(64), bf16 hi+lo) ----
    uint32_t qhi[4][4], qlo[4][4];
    {
        const float* Qb = Q + ((size_t)bh * Nn + q0 + 16 * w) * DHd;
        #pragma unroll
        for (int ks = 0; ks < 4; ++ks) {
            #pragma unroll
            for (int r = 0; r < 4; ++r) {
                const int row = gq + (r & 1) * 8;            // a0,a2: gq ; a1,a3: gq+8
                const int col = 16*ks + 2*j4 + (r >> 1) * 8; // a0,a1: +0 ; a2,a3: +8
                float2 v = *(const float2*)(Qb + row * 64 + col);
                v.x *= 0.125f; v.y *= 0.125f;
                uint32_t h = pk(v.x, v.y);
                qhi[ks][r] = h;
                qlo[ks][r] = pk(rlo(v.x, h), rhi(v.y, h));
            }
        }
    }

    float ctx[8][4];
    #pragma unroll
    for (int ni = 0; ni < 8; ++ni)
        #pragma unroll
        for (int q = 0; q < 4; ++q) ctx[ni][q] = 0.f;
    float m0 = -1e30f, m1 = -1e30f, l0 = 0.f, l1 = 0.f;

    // ---- initial fill of buffer 0 ----
    float kr[16], vr[16];
    ldg_kv(Kb, Vb, tid, kr, vr);
    sts_kv(smb, tid, kr, vr);
    __syncthreads();
    ldg_kv(Kb + 64*64, Vb + 64*64, tid, kr, vr);   // prefetch tile 1

    for (int kt = 0; kt < 32; ++kt) {
        const __nv_bfloat16* Ks = smb + (kt & 1) * ABUF;
        const __nv_bfloat16* Kl = Ks + 4608;
        const __nv_bfloat16* Vh = Ks + 9216;
        const __nv_bfloat16* Vl = Ks + 13824;

        // ---- S = Q K^T (3-term bf16x2) ----
        float sacc[8][4];
        #pragma unroll
        for (int ni = 0; ni < 8; ++ni)
            #pragma unroll
            for (int q = 0; q < 4; ++q) sacc[ni][q] = 0.f;

        #pragma unroll
        for (int ks = 0; ks < 4; ++ks) {
            #pragma unroll
            for (int ni = 0; ni < 8; ++ni) {
                const int off = (8*ni + gq) * 72 + 16*ks + 2*j4;
                uint32_t bh0 = *(const uint32_t*)(Ks + off);
                uint32_t bh1 = *(const uint32_t*)(Ks + off + 8);
                uint32_t bl0 = *(const uint32_t*)(Kl + off);
                uint32_t bl1 = *(const uint32_t*)(Kl + off + 8);
                MMA_BF16(sacc[ni], qhi[ks], bh0, bh1);
                MMA_BF16(sacc[ni], qhi[ks], bl0, bl1);
                MMA_BF16(sacc[ni], qlo[ks], bh0, bh1);
            }
        }

        // ---- online softmax (rows gq and gq+8; quad reduction) ----
        float mx0 = -1e30f, mx1 = -1e30f;
        #pragma unroll
        for (int ni = 0; ni < 8; ++ni) {
            mx0 = fmaxf(mx0, fmaxf(sacc[ni][0], sacc[ni][1]));
            mx1 = fmaxf(mx1, fmaxf(sacc[ni][2], sacc[ni][3]));
        }
        mx0 = fmaxf(mx0, __shfl_xor_sync(0xffffffffu, mx0, 1));
        mx0 = fmaxf(mx0, __shfl_xor_sync(0xffffffffu, mx0, 2));
        mx1 = fmaxf(mx1, __shfl_xor_sync(0xffffffffu, mx1, 1));
        mx1 = fmaxf(mx1, __shfl_xor_sync(0xffffffffu, mx1, 2));
        const float mn0 = fmaxf(m0, mx0), mn1 = fmaxf(m1, mx1);
        const float a0 = __expf(m0 - mn0), a1 = __expf(m1 - mn1);
        m0 = mn0; m1 = mn1;

        float rs0 = 0.f, rs1 = 0.f;
        #pragma unroll
        for (int ni = 0; ni < 8; ++ni) {
            sacc[ni][0] = __expf(sacc[ni][0] - mn0);
            sacc[ni][1] = __expf(sacc[ni][1] - mn0);
            sacc[ni][2] = __expf(sacc[ni][2] - mn1);
            sacc[ni][3] = __expf(sacc[ni][3] - mn1);
            rs0 += sacc[ni][0] + sacc[ni][1];
            rs1 += sacc[ni][2] + sacc[ni][3];
        }
        rs0 += __shfl_xor_sync(0xffffffffu, rs0, 1);
        rs0 += __shfl_xor_sync(0xffffffffu, rs0, 2);
        rs1 += __shfl_xor_sync(0xffffffffu, rs1, 1);
        rs1 += __shfl_xor_sync(0xffffffffu, rs1, 2);
        l0 = l0 * a0 + rs0;
        l1 = l1 * a1 + rs1;

        #pragma unroll
        for (int ni = 0; ni < 8; ++ni) {
            ctx[ni][0] *= a0; ctx[ni][1] *= a0;
            ctx[ni][2] *= a1; ctx[ni][3] *= a1;
        }

        // ---- P fragments (register reuse of S accumulators, FA2 layout) ----
        uint32_t phi[4][4], plo[4][4];
        #pragma unroll
        for (int ks = 0; ks < 4; ++ks) {
            const float* t0 = sacc[2*ks];
            const float* t1 = sacc[2*ks + 1];
            uint32_t h;
            h = pk(t0[0], t0[1]); phi[ks][0] = h; plo[ks][0] = pk(rlo(t0[0], h), rhi(t0[1], h));
            h = pk(t0[2], t0[3]); phi[ks][1] = h; plo[ks][1] = pk(rlo(t0[2], h), rhi(t0[3], h));
            h = pk(t1[0], t1[1]); phi[ks][2] = h; plo[ks][2] = pk(rlo(t1[0], h), rhi(t1[1], h));
            h = pk(t1[2], t1[3]); phi[ks][3] = h; plo[ks][3] = pk(rlo(t1[2], h), rhi(t1[3], h));
        }

        // ---- ctx += P V (3-term bf16x2) ----
        #pragma unroll
        for (int ks = 0; ks < 4; ++ks) {
            #pragma unroll
            for (int ni = 0; ni < 8; ++ni) {
                const int off = (8*ni + gq) * 72 + 16*ks + 2*j4;
                uint32_t bh0 = *(const uint32_t*)(Vh + off);
                uint32_t bh1 = *(const uint32_t*)(Vh + off + 8);
                uint32_t bl0 = *(const uint32_t*)(Vl + off);
                uint32_t bl1 = *(const uint32_t*)(Vl + off + 8);
                MMA_BF16(ctx[ni], phi[ks], bh0, bh1);
                MMA_BF16(ctx[ni], phi[ks], bl0, bl1);
                MMA_BF16(ctx[ni], plo[ks], bh0, bh1);
            }
        }

        // ---- double-buffer refill ----
        if (kt < 31) {
            sts_kv(smb + ((kt + 1) & 1) * ABUF, tid, kr, vr);
            const int nxt = (kt + 2 < 32) ? kt + 2 : 31;
            ldg_kv(Kb + (size_t)nxt * 64 * 64, Vb + (size_t)nxt * 64 * 64, tid, kr, vr);
            __syncthreads();
        }
    }

    // ---- epilogue: normalize, write (b, n, h*64+dh) ----
    const int bb = bh >> 4;
    const int hh = bh & 15;
    const float il0 = 1.0f / l0, il1 = 1.0f / l1;
    const int n0 = q0 + 16 * w + gq;
    float* O0 = O + (((size_t)bb * Nn + n0) * Hh + hh) * DHd;
    float* O1 = O + (((size_t)bb * Nn + n0 + 8) * Hh + hh) * DHd;
    #pragma unroll
    for (int ni = 0; ni < 8; ++ni) {
        const int col = 8*ni + 2*j4;
        *(float2*)(O0 + col) = make_float2(ctx[ni][0] * il0, ctx[ni][1] * il0);
        *(float2*)(O1 + col) = make_float2(ctx[ni][2] * il1, ctx[ni][3] * il1);
    }
}

// ---------------- launch ---------------------------------------------------------
extern "C" void kernel_launch(void* const* d_in, const int* in_sizes, int n_in,
                              void* d_out, int out_size)
{
    const float* queries = (const float*)d_in[0];
    const float* keys    = (const float*)d_in[1];
    const float* values  = (const float*)d_in[2];
    const float* Wq      = (const float*)d_in[3];
    const float* Wk      = (const float*)d_in[4];
    const float* Wv      = (const float*)d_in[5];
    const float* Wo      = (const float*)d_in[6];
    float* out = (float*)d_out;

    float *qp, *kp, *vp, *cp;
    cudaGetSymbolAddress((void**)&qp, g_q);
    cudaGetSymbolAddress((void**)&kp, g_k);
    cudaGetSymbolAddress((void**)&vp, g_v);
    cudaGetSymbolAddress((void**)&cp, g_ctx);

    dim3 ggrid(1024/128, MTOT/128);   // (8, 64)
    gemm_mma<1><<<ggrid, 256>>>(queries, Wq, qp);
    gemm_mma<1><<<ggrid, 256>>>(keys,    Wk, kp);
    gemm_mma<1><<<ggrid, 256>>>(values,  Wv, vp);

    const int asmem = 2 * ABUF * (int)sizeof(__nv_bfloat16);   // 73728 B
    cudaFuncSetAttribute(attn_mma,
                         cudaFuncAttributeMaxDynamicSharedMemorySize, asmem);
    dim3 agrid(Nn/128, Bb*Hh);        // (16, 64)
    attn_mma<<<agrid, 256, asmem>>>(qp, kp, vp, cp);

    gemm_mma<0><<<ggrid, 256>>>(cp, Wo, out);
}